// round 7
// baseline (speedup 1.0000x reference)
#include <cuda_runtime.h>
#include <cuda_fp16.h>
#include <stdint.h>

typedef unsigned long long ull;
typedef unsigned int u32;

#define M_PTS 16384
#define D_DIM 256
#define C_CODES 8192

#define BM 128
#define BN 256
#define BK 32
#define NKB (D_DIM / BK)          // 8 k-chunks
#define STRIDE 40                 // halfs per smem row (padded, conflict-free)
#define NTILES (C_CODES / BN)     // 32 C-tiles of 256 codes
#define MARGIN 2.5e-3f            // >= 2x worst-case |d2_approx - d2_exact|

// P1 stage: Ah + Bh only
#define OFF_AH 0
#define OFF_BH (BM * STRIDE)                      // 5120 halfs
#define STAGE_HALFS ((BM + BN) * STRIDE)          // 15360
#define STAGE_BYTES (STAGE_HALFS * 2)             // 30720
#define SMEM_P1 (2 * STAGE_BYTES + BN * 4 + BM * 4)   // + e2 + tmin = 62976

// P2: 64 codes transposed [256][66] + e2[64]
#define P2_STRIDE 66
#define SMEM_P2 (256 * P2_STRIDE * 4 + 64 * 4)    // 67840

// ---------------------------------------------------------------------------
// Static scratch (no cudaMalloc allowed)
__device__ __align__(16) __half g_Xh[M_PTS * D_DIM];
__device__ __align__(16) __half g_Eh[C_CODES * D_DIM];
__device__ ull   g_best[M_PTS];
__device__ u32   g_amin[M_PTS];
__device__ u32   g_tmin[M_PTS * NTILES];
__device__ int   g_cnt[NTILES];
__device__ int   g_list[NTILES * M_PTS];
__device__ float g_x2[M_PTS];
__device__ float g_e2[C_CODES];

// ---------------------------------------------------------------------------
__device__ __forceinline__ u32 smem_u32(const void* p) {
    u32 a;
    asm("{ .reg .u64 t; cvta.to.shared.u64 t, %1; cvt.u32.u64 %0, t; }" : "=r"(a) : "l"(p));
    return a;
}
__device__ __forceinline__ void cp16(u32 dst, const void* src) {
    asm volatile("cp.async.cg.shared.global [%0], [%1], 16;" :: "r"(dst), "l"(src));
}
__device__ __forceinline__ void cp_commit() {
    asm volatile("cp.async.commit_group;" ::: "memory");
}
template <int N>
__device__ __forceinline__ void cp_wait() {
    asm volatile("cp.async.wait_group %0;" :: "n"(N) : "memory");
}
__device__ __forceinline__ void mma16816(float* c, u32 a0, u32 a1, u32 a2, u32 a3,
                                         u32 b0, u32 b1) {
    asm volatile(
        "mma.sync.aligned.m16n8k16.row.col.f32.f16.f16.f32 "
        "{%0,%1,%2,%3}, {%4,%5,%6,%7}, {%8,%9}, {%0,%1,%2,%3};"
        : "+f"(c[0]), "+f"(c[1]), "+f"(c[2]), "+f"(c[3])
        : "r"(a0), "r"(a1), "r"(a2), "r"(a3), "r"(b0), "r"(b1));
}
__device__ __forceinline__ void ldsm_x4(u32* r, u32 addr) {
    asm volatile("ldmatrix.sync.aligned.m8n8.x4.shared.b16 {%0,%1,%2,%3}, [%4];"
                 : "=r"(r[0]), "=r"(r[1]), "=r"(r[2]), "=r"(r[3]) : "r"(addr));
}

// ---------------------------------------------------------------------------
__global__ void init_kernel(ull* best, u32* amin, int* cnt) {
    int i = blockIdx.x * blockDim.x + threadIdx.x;
    if (i < M_PTS) { best[i] = 0xFFFFFFFFFFFFFFFFull; amin[i] = 0xFFFFFFFFu; }
    if (i < NTILES) cnt[i] = 0;
}

// row sum of squares (exact recipe that gave rel_err == 0 since round 1)
__global__ void rowsumsq_kernel(const float* __restrict__ a, float* __restrict__ out, int rows) {
    int row = blockIdx.x * (blockDim.x >> 5) + (threadIdx.x >> 5);
    int lane = threadIdx.x & 31;
    if (row >= rows) return;
    const float* p = a + (size_t)row * D_DIM;
    float acc = 0.0f;
#pragma unroll
    for (int i = 0; i < D_DIM / 32; i++) {
        float v = p[lane + 32 * i];
        acc = __fadd_rn(acc, __fmul_rn(v, v));
    }
#pragma unroll
    for (int o = 16; o >= 1; o >>= 1)
        acc = __fadd_rn(acc, __shfl_down_sync(0xFFFFFFFFu, acc, o));
    if (lane == 0) out[row] = acc;
}

// fp32 -> hi fp16, row-major
__global__ void split_hi_kernel(const float* __restrict__ src, __half* __restrict__ dh, int n4) {
    int idx = blockIdx.x * blockDim.x + threadIdx.x;
    if (idx >= n4) return;
    float4 v = ((const float4*)src)[idx];
    __half2 a = __halves2half2(__float2half_rn(v.x), __float2half_rn(v.y));
    __half2 b = __halves2half2(__float2half_rn(v.z), __float2half_rn(v.w));
    uint2 p;
    p.x = *(u32*)&a;
    p.y = *(u32*)&b;
    *(uint2*)(dh + (size_t)idx * 4) = p;
}

// ---------------------------------------------------------------------------
// P1: hi-only HMMA GEMM -> per-(point, tile) approx-min + global approx-min.
// Grid (NTILES=32, M/BM=128) = 4096 CTAs, 256 threads, 2 CTAs/SM.
__global__ __launch_bounds__(256, 2)
void p1_kernel(const float* __restrict__ x2g, const float* __restrict__ e2g,
               u32* __restrict__ tmin_g, u32* __restrict__ amin_g) {
    extern __shared__ __half smh[];
    const u32 sb = smem_u32(smh);
    const int tid = threadIdx.x;
    const int lane = tid & 31;
    const int wid = tid >> 5;
    const int warp_m = wid & 1;       // 64-row halves
    const int warp_n = wid >> 1;      // 0..3 -> 64-col slices

    const int mrow0 = blockIdx.y * BM;
    const int tile = blockIdx.x;
    const int crow0 = tile * BN;

    float* e2s   = (float*)((char*)smh + 2 * STAGE_BYTES);
    u32* tmin_s  = (u32*)((char*)smh + 2 * STAGE_BYTES + BN * 4);
    e2s[tid] = e2g[crow0 + tid];
    if (tid < BM) tmin_s[tid] = 0xFFFFFFFFu;

    // ---- cp.async stage loader: 1536 16B tasks, 6 per thread ----
    auto issue = [&](int kb) {
        u32 sbase = sb + (u32)(kb & 1) * STAGE_BYTES;
        int kcol = kb * BK;
#pragma unroll
        for (int i = 0; i < 6; i++) {
            int t = tid + i * 256;
            if (t < 512) {
                int r = t >> 2, c = t & 3;
                const __half* g = g_Xh + (size_t)(mrow0 + r) * D_DIM + kcol + c * 8;
                cp16(sbase + (u32)(OFF_AH + r * STRIDE + c * 8) * 2, g);
            } else {
                int t2 = t - 512;
                int r = t2 >> 2, c = t2 & 3;
                const __half* g = g_Eh + (size_t)(crow0 + r) * D_DIM + kcol + c * 8;
                cp16(sbase + (u32)(OFF_BH + r * STRIDE + c * 8) * 2, g);
            }
        }
        cp_commit();
    };

    float acc[4][8][4];
#pragma unroll
    for (int mt = 0; mt < 4; mt++)
#pragma unroll
        for (int nt = 0; nt < 8; nt++)
#pragma unroll
            for (int r = 0; r < 4; r++) acc[mt][nt][r] = 0.0f;

    issue(0);

    const int a_r = (lane & 7) + ((lane >> 3) & 1) * 8;
    const int a_k = (lane >> 4) * 8;
    const int b_r = (lane & 7) + (lane >> 4) * 8;
    const int b_k = ((lane >> 3) & 1) * 8;

    u32 aoff[4], boff[4];
#pragma unroll
    for (int mt = 0; mt < 4; mt++)
        aoff[mt] = (u32)((OFF_AH + (warp_m * 64 + mt * 16 + a_r) * STRIDE + a_k) * 2);
#pragma unroll
    for (int p = 0; p < 4; p++)
        boff[p] = (u32)((OFF_BH + (warp_n * 64 + p * 16 + b_r) * STRIDE + b_k) * 2);

    // Single-barrier pipeline: reads of stage s (iter kb-1) always precede the
    // barrier of iter kb, which precedes issue(kb+1)'s overwrite of stage s.
    for (int kb = 0; kb < NKB; kb++) {
        cp_wait<0>();
        __syncthreads();
        if (kb + 1 < NKB) issue(kb + 1);

        const u32 sbase = sb + (u32)(kb & 1) * STAGE_BYTES;
#pragma unroll
        for (int ks = 0; ks < 2; ks++) {
            const u32 kbyte = (u32)(ks * 32);
            u32 af[4][4], bf[4][4];
#pragma unroll
            for (int mt = 0; mt < 4; mt++) ldsm_x4(af[mt], sbase + aoff[mt] + kbyte);
#pragma unroll
            for (int p = 0; p < 4; p++) ldsm_x4(bf[p], sbase + boff[p] + kbyte);
#pragma unroll
            for (int mt = 0; mt < 4; mt++)
#pragma unroll
                for (int nt = 0; nt < 8; nt++) {
                    const u32* b = bf[nt >> 1];
                    int o = (nt & 1) * 2;
                    mma16816(acc[mt][nt], af[mt][0], af[mt][1], af[mt][2], af[mt][3],
                             b[o], b[o + 1]);
                }
        }
    }
    __syncthreads();

    // ---- epilogue: approx d2, per-point tile-min via smem atomics ----
#pragma unroll
    for (int mt = 0; mt < 4; mt++) {
#pragma unroll
        for (int rh = 0; rh < 2; rh++) {
            int rlocal = warp_m * 64 + mt * 16 + rh * 8 + (lane >> 2);
            float x2v = x2g[mrow0 + rlocal];
            float vmin = 3.4e38f;
#pragma unroll
            for (int nt = 0; nt < 8; nt++) {
#pragma unroll
                for (int cc = 0; cc < 2; cc++) {
                    int cl = warp_n * 64 + nt * 8 + (lane & 3) * 2 + cc;
                    float t = __fadd_rn(x2v, -2.0f * acc[mt][nt][rh * 2 + cc]);
                    float d2 = __fadd_rn(t, e2s[cl]);
                    vmin = (d2 < vmin) ? d2 : vmin;
                }
            }
            atomicMin(&tmin_s[rlocal], __float_as_uint(vmin));
        }
    }
    __syncthreads();

    if (tid < BM) {
        u32 tb = tmin_s[tid];
        tmin_g[(size_t)(mrow0 + tid) * NTILES + tile] = tb;
        atomicMin(&amin_g[mrow0 + tid], tb);
    }
}

// ---------------------------------------------------------------------------
// Candidate tile selection.
__global__ void select_kernel(const u32* __restrict__ tmin_g, const u32* __restrict__ amin_g,
                              int* __restrict__ cnt, int* __restrict__ list) {
    int idx = blockIdx.x * blockDim.x + threadIdx.x;
    if (idx >= M_PTS * NTILES) return;
    int m = idx >> 5;                 // NTILES = 32
    int t = idx & (NTILES - 1);
    float tv = __uint_as_float(tmin_g[idx]);
    float gm = __uint_as_float(amin_g[m]);
    if (tv <= gm + MARGIN) {
        int p = atomicAdd(&cnt[t], 1);
        list[t * M_PTS + p] = m;
    }
}

// ---------------------------------------------------------------------------
// P2: exact fp32 rescore. Grid 128 = 32 tiles x 4 quarters (64 codes each).
// Codes transposed in smem; per job: shfl-broadcast x dims, 2 codes per lane.
__global__ __launch_bounds__(256, 1)
void p2_kernel(const float* __restrict__ X, const float* __restrict__ E,
               const float* __restrict__ x2g, const float* __restrict__ e2g,
               const int* __restrict__ cnt_g, const int* __restrict__ list_g,
               ull* __restrict__ best) {
    extern __shared__ float sc[];     // sc[d * 66 + c], d<256, c<64; then e2[64]
    const int tile = blockIdx.x >> 2;
    const int quarter = blockIdx.x & 3;
    const int c0 = tile * BN + quarter * 64;
    const int tid = threadIdx.x;

    for (int i = tid; i < 64 * 256; i += 256) {
        int c = i >> 8, d = i & 255;
        sc[d * P2_STRIDE + c] = E[(size_t)(c0 + c) * D_DIM + d];
    }
    float* se2 = sc + 256 * P2_STRIDE;
    if (tid < 64) se2[tid] = e2g[c0 + tid];
    __syncthreads();

    const int lane = tid & 31;
    const int wid = tid >> 5;
    const int cnt = cnt_g[tile];

    for (int pi = wid; pi < cnt; pi += 8) {
        int m = list_g[tile * M_PTS + pi];
        float xr[8];
#pragma unroll
        for (int j = 0; j < 8; j++) xr[j] = X[(size_t)m * D_DIM + j * 32 + lane];

        float a0 = 0.0f, a1 = 0.0f, b0 = 0.0f, b1 = 0.0f;
#pragma unroll
        for (int j = 0; j < 8; j++) {
#pragma unroll
            for (int l = 0; l < 32; l++) {
                float xd = __shfl_sync(0xFFFFFFFFu, xr[j], l);
                float2 ev = *(const float2*)&sc[(j * 32 + l) * P2_STRIDE + 2 * lane];
                if (j & 1) { b0 = __fmaf_rn(xd, ev.x, b0); b1 = __fmaf_rn(xd, ev.y, b1); }
                else       { a0 = __fmaf_rn(xd, ev.x, a0); a1 = __fmaf_rn(xd, ev.y, a1); }
            }
        }
        float xe0 = __fadd_rn(a0, b0);
        float xe1 = __fadd_rn(a1, b1);

        float x2v = x2g[m];
        float d20 = __fadd_rn(__fadd_rn(x2v, -2.0f * xe0), se2[2 * lane]);
        float d21 = __fadd_rn(__fadd_rn(x2v, -2.0f * xe1), se2[2 * lane + 1]);
        ull k0 = ((ull)__float_as_uint(d20) << 32) | (u32)(c0 + 2 * lane);
        ull k1 = ((ull)__float_as_uint(d21) << 32) | (u32)(c0 + 2 * lane + 1);
        ull kb = (k1 < k0) ? k1 : k0;
#pragma unroll
        for (int o = 16; o >= 1; o >>= 1) {
            ull other = __shfl_xor_sync(0xFFFFFFFFu, kb, o);
            kb = (other < kb) ? other : kb;
        }
        if (lane == 0) atomicMin(&best[m], kb);
    }
}

// ---------------------------------------------------------------------------
__global__ void finalize_kernel(const float* __restrict__ E,
                                const ull* __restrict__ best,
                                float* __restrict__ out_q,
                                float* __restrict__ out_ind, int write_ind) {
    int row = blockIdx.x * (blockDim.x >> 5) + (threadIdx.x >> 5);
    int lane = threadIdx.x & 31;
    if (row >= M_PTS) return;
    u32 idx = (u32)(best[row] & 0xFFFFFFFFu);
    const float4* src = (const float4*)(E + (size_t)idx * D_DIM);
    float4* dst = (float4*)(out_q + (size_t)row * D_DIM);
    dst[lane]      = src[lane];
    dst[lane + 32] = src[lane + 32];
    if (write_ind && lane == 0) out_ind[row] = (float)idx;
}

// ---------------------------------------------------------------------------
extern "C" void kernel_launch(void* const* d_in, const int* in_sizes, int n_in,
                              void* d_out, int out_size) {
    const float* X = (const float*)d_in[0];
    const float* E = (const float*)d_in[1];
    if (n_in >= 2 && in_sizes[0] == C_CODES * D_DIM && in_sizes[1] == M_PTS * D_DIM) {
        X = (const float*)d_in[1];
        E = (const float*)d_in[0];
    }

    float* out_q = (float*)d_out;
    int write_ind = (out_size >= M_PTS * D_DIM + M_PTS) ? 1 : 0;
    float* out_ind = out_q + (size_t)M_PTS * D_DIM;

    ull* best; u32 *amin, *tmin; int *cnt, *list;
    float *x2p, *e2p; __half *xh, *eh;
    cudaGetSymbolAddress((void**)&best, g_best);
    cudaGetSymbolAddress((void**)&amin, g_amin);
    cudaGetSymbolAddress((void**)&tmin, g_tmin);
    cudaGetSymbolAddress((void**)&cnt, g_cnt);
    cudaGetSymbolAddress((void**)&list, g_list);
    cudaGetSymbolAddress((void**)&x2p, g_x2);
    cudaGetSymbolAddress((void**)&e2p, g_e2);
    cudaGetSymbolAddress((void**)&xh, g_Xh);
    cudaGetSymbolAddress((void**)&eh, g_Eh);

    init_kernel<<<(M_PTS + 255) / 256, 256>>>(best, amin, cnt);
    rowsumsq_kernel<<<(M_PTS + 7) / 8, 256>>>(X, x2p, M_PTS);
    rowsumsq_kernel<<<(C_CODES + 7) / 8, 256>>>(E, e2p, C_CODES);
    split_hi_kernel<<<(M_PTS * 64 + 255) / 256, 256>>>(X, xh, M_PTS * 64);
    split_hi_kernel<<<(C_CODES * 64 + 255) / 256, 256>>>(E, eh, C_CODES * 64);

    cudaFuncSetAttribute(p1_kernel, cudaFuncAttributeMaxDynamicSharedMemorySize, SMEM_P1);
    dim3 g1(NTILES, M_PTS / BM);
    p1_kernel<<<g1, 256, SMEM_P1>>>(x2p, e2p, tmin, amin);

    select_kernel<<<(M_PTS * NTILES + 255) / 256, 256>>>(tmin, amin, cnt, list);

    cudaFuncSetAttribute(p2_kernel, cudaFuncAttributeMaxDynamicSharedMemorySize, SMEM_P2);
    p2_kernel<<<4 * NTILES, 256, SMEM_P2>>>(X, E, x2p, e2p, cnt, list, best);

    finalize_kernel<<<(M_PTS + 7) / 8, 256>>>(E, best, out_q, out_ind, write_ind);
}

// round 8
// speedup vs baseline: 1.8375x; 1.8375x over previous
#include <cuda_runtime.h>
#include <cuda_fp16.h>
#include <stdint.h>

typedef unsigned long long ull;
typedef unsigned int u32;

#define M_PTS 16384
#define D_DIM 256
#define C_CODES 8192

#define BM 128
#define BN 128
#define BK 32
#define NKB (D_DIM / BK)          // 8 k-chunks
#define STRIDE 40                 // halfs per smem row (padded, conflict-free)
#define NTILES (C_CODES / BN)     // 64 C-tiles of 128 codes
#define MARGIN 2.5e-3f            // >= 2x worst-case |d2_approx - d2_exact|

// P1 stage: Ah + Bh only
#define OFF_AH 0
#define OFF_BH (BM * STRIDE)                      // 5120 halfs
#define STAGE_HALFS ((BM + BN) * STRIDE)          // 10240
#define STAGE_BYTES (STAGE_HALFS * 2)             // 20480
#define SMEM_P1 (2 * STAGE_BYTES + BN * 4 + BM * 4)   // + e2 + tmin = 41984

// P2: 64 codes transposed [256][66] + e2[64]
#define P2_STRIDE 66
#define SMEM_P2 (256 * P2_STRIDE * 4 + 64 * 4)    // 67840

// ---------------------------------------------------------------------------
// Static scratch (no cudaMalloc allowed)
__device__ __align__(16) __half g_Xh[M_PTS * D_DIM];
__device__ __align__(16) __half g_Eh[C_CODES * D_DIM];
__device__ ull   g_best[M_PTS];
__device__ u32   g_amin[M_PTS];
__device__ u32   g_tmin[M_PTS * NTILES];
__device__ int   g_cnt[NTILES];
__device__ int   g_list[NTILES * M_PTS];
__device__ float g_x2[M_PTS];
__device__ float g_e2[C_CODES];

// ---------------------------------------------------------------------------
__device__ __forceinline__ u32 smem_u32(const void* p) {
    u32 a;
    asm("{ .reg .u64 t; cvta.to.shared.u64 t, %1; cvt.u32.u64 %0, t; }" : "=r"(a) : "l"(p));
    return a;
}
__device__ __forceinline__ void cp16(u32 dst, const void* src) {
    asm volatile("cp.async.cg.shared.global [%0], [%1], 16;" :: "r"(dst), "l"(src));
}
__device__ __forceinline__ void cp_commit() {
    asm volatile("cp.async.commit_group;" ::: "memory");
}
template <int N>
__device__ __forceinline__ void cp_wait() {
    asm volatile("cp.async.wait_group %0;" :: "n"(N) : "memory");
}
__device__ __forceinline__ void mma16816(float* c, u32 a0, u32 a1, u32 a2, u32 a3,
                                         u32 b0, u32 b1) {
    asm volatile(
        "mma.sync.aligned.m16n8k16.row.col.f32.f16.f16.f32 "
        "{%0,%1,%2,%3}, {%4,%5,%6,%7}, {%8,%9}, {%0,%1,%2,%3};"
        : "+f"(c[0]), "+f"(c[1]), "+f"(c[2]), "+f"(c[3])
        : "r"(a0), "r"(a1), "r"(a2), "r"(a3), "r"(b0), "r"(b1));
}
__device__ __forceinline__ void ldsm_x4(u32* r, u32 addr) {
    asm volatile("ldmatrix.sync.aligned.m8n8.x4.shared.b16 {%0,%1,%2,%3}, [%4];"
                 : "=r"(r[0]), "=r"(r[1]), "=r"(r[2]), "=r"(r[3]) : "r"(addr));
}

// ---------------------------------------------------------------------------
__global__ void init_kernel(ull* best, u32* amin, int* cnt) {
    int i = blockIdx.x * blockDim.x + threadIdx.x;
    if (i < M_PTS) { best[i] = 0xFFFFFFFFFFFFFFFFull; amin[i] = 0xFFFFFFFFu; }
    if (i < NTILES) cnt[i] = 0;
}

// row sum of squares (exact recipe that gave rel_err == 0 since round 1)
__global__ void rowsumsq_kernel(const float* __restrict__ a, float* __restrict__ out, int rows) {
    int row = blockIdx.x * (blockDim.x >> 5) + (threadIdx.x >> 5);
    int lane = threadIdx.x & 31;
    if (row >= rows) return;
    const float* p = a + (size_t)row * D_DIM;
    float acc = 0.0f;
#pragma unroll
    for (int i = 0; i < D_DIM / 32; i++) {
        float v = p[lane + 32 * i];
        acc = __fadd_rn(acc, __fmul_rn(v, v));
    }
#pragma unroll
    for (int o = 16; o >= 1; o >>= 1)
        acc = __fadd_rn(acc, __shfl_down_sync(0xFFFFFFFFu, acc, o));
    if (lane == 0) out[row] = acc;
}

// fp32 -> hi fp16, row-major
__global__ void split_hi_kernel(const float* __restrict__ src, __half* __restrict__ dh, int n4) {
    int idx = blockIdx.x * blockDim.x + threadIdx.x;
    if (idx >= n4) return;
    float4 v = ((const float4*)src)[idx];
    __half2 a = __halves2half2(__float2half_rn(v.x), __float2half_rn(v.y));
    __half2 b = __halves2half2(__float2half_rn(v.z), __float2half_rn(v.w));
    uint2 p;
    p.x = *(u32*)&a;
    p.y = *(u32*)&b;
    *(uint2*)(dh + (size_t)idx * 4) = p;
}

// ---------------------------------------------------------------------------
// P1: hi-only HMMA GEMM -> per-(point, tile) approx-min + global approx-min.
// Grid (NTILES=64, M/BM=128) = 8192 CTAs, 256 threads, 2 CTAs/SM, no spill.
__global__ __launch_bounds__(256, 2)
void p1_kernel(const float* __restrict__ x2g, const float* __restrict__ e2g,
               u32* __restrict__ tmin_g, u32* __restrict__ amin_g) {
    extern __shared__ __half smh[];
    const u32 sb = smem_u32(smh);
    const int tid = threadIdx.x;
    const int lane = tid & 31;
    const int wid = tid >> 5;
    const int warp_m = wid & 1;       // 64-row halves
    const int warp_n = wid >> 1;      // 0..3 -> 32-col slices

    const int mrow0 = blockIdx.y * BM;
    const int tile = blockIdx.x;
    const int crow0 = tile * BN;

    float* e2s  = (float*)((char*)smh + 2 * STAGE_BYTES);
    u32* tmin_s = (u32*)((char*)smh + 2 * STAGE_BYTES + BN * 4);
    if (tid < BN) e2s[tid] = e2g[crow0 + tid];
    if (tid < BM) tmin_s[tid] = 0xFFFFFFFFu;

    // ---- cp.async stage loader: 1024 16B tasks, 4 per thread ----
    auto issue = [&](int kb) {
        u32 sbase = sb + (u32)(kb & 1) * STAGE_BYTES;
        int kcol = kb * BK;
#pragma unroll
        for (int i = 0; i < 4; i++) {
            int t = tid + i * 256;
            if (t < 512) {
                int r = t >> 2, c = t & 3;
                const __half* g = g_Xh + (size_t)(mrow0 + r) * D_DIM + kcol + c * 8;
                cp16(sbase + (u32)(OFF_AH + r * STRIDE + c * 8) * 2, g);
            } else {
                int t2 = t - 512;
                int r = t2 >> 2, c = t2 & 3;
                const __half* g = g_Eh + (size_t)(crow0 + r) * D_DIM + kcol + c * 8;
                cp16(sbase + (u32)(OFF_BH + r * STRIDE + c * 8) * 2, g);
            }
        }
        cp_commit();
    };

    float acc[4][4][4];
#pragma unroll
    for (int mt = 0; mt < 4; mt++)
#pragma unroll
        for (int nt = 0; nt < 4; nt++)
#pragma unroll
            for (int r = 0; r < 4; r++) acc[mt][nt][r] = 0.0f;

    issue(0);

    const int a_r = (lane & 7) + ((lane >> 3) & 1) * 8;
    const int a_k = (lane >> 4) * 8;
    const int b_r = (lane & 7) + (lane >> 4) * 8;
    const int b_k = ((lane >> 3) & 1) * 8;

    u32 aoff[4], boff[2];
#pragma unroll
    for (int mt = 0; mt < 4; mt++)
        aoff[mt] = (u32)((OFF_AH + (warp_m * 64 + mt * 16 + a_r) * STRIDE + a_k) * 2);
#pragma unroll
    for (int p = 0; p < 2; p++)
        boff[p] = (u32)((OFF_BH + (warp_n * 32 + p * 16 + b_r) * STRIDE + b_k) * 2);

    // Single-barrier 2-stage pipeline: wait for stage kb, barrier, then kick
    // off kb+1 (other buffer) and compute kb.
    for (int kb = 0; kb < NKB; kb++) {
        cp_wait<0>();
        __syncthreads();
        if (kb + 1 < NKB) issue(kb + 1);

        const u32 sbase = sb + (u32)(kb & 1) * STAGE_BYTES;
#pragma unroll
        for (int ks = 0; ks < 2; ks++) {
            const u32 kbyte = (u32)(ks * 32);
            u32 af[4][4], bf[2][4];
#pragma unroll
            for (int mt = 0; mt < 4; mt++) ldsm_x4(af[mt], sbase + aoff[mt] + kbyte);
#pragma unroll
            for (int p = 0; p < 2; p++) ldsm_x4(bf[p], sbase + boff[p] + kbyte);
#pragma unroll
            for (int mt = 0; mt < 4; mt++)
#pragma unroll
                for (int nt = 0; nt < 4; nt++) {
                    const u32* b = bf[nt >> 1];
                    int o = (nt & 1) * 2;
                    mma16816(acc[mt][nt], af[mt][0], af[mt][1], af[mt][2], af[mt][3],
                             b[o], b[o + 1]);
                }
        }
    }
    __syncthreads();

    // ---- epilogue: approx d2, per-point tile-min via smem atomics ----
#pragma unroll
    for (int mt = 0; mt < 4; mt++) {
#pragma unroll
        for (int rh = 0; rh < 2; rh++) {
            int rlocal = warp_m * 64 + mt * 16 + rh * 8 + (lane >> 2);
            float x2v = x2g[mrow0 + rlocal];
            float vmin = 3.4e38f;
#pragma unroll
            for (int nt = 0; nt < 4; nt++) {
#pragma unroll
                for (int cc = 0; cc < 2; cc++) {
                    int cl = warp_n * 32 + nt * 8 + (lane & 3) * 2 + cc;
                    float t = __fadd_rn(x2v, -2.0f * acc[mt][nt][rh * 2 + cc]);
                    float d2 = __fadd_rn(t, e2s[cl]);
                    vmin = (d2 < vmin) ? d2 : vmin;
                }
            }
            atomicMin(&tmin_s[rlocal], __float_as_uint(vmin));
        }
    }
    __syncthreads();

    if (tid < BM) {
        u32 tb = tmin_s[tid];
        tmin_g[(size_t)(mrow0 + tid) * NTILES + tile] = tb;
        atomicMin(&amin_g[mrow0 + tid], tb);
    }
}

// ---------------------------------------------------------------------------
// Candidate tile selection.
__global__ void select_kernel(const u32* __restrict__ tmin_g, const u32* __restrict__ amin_g,
                              int* __restrict__ cnt, int* __restrict__ list) {
    int idx = blockIdx.x * blockDim.x + threadIdx.x;
    if (idx >= M_PTS * NTILES) return;
    int m = idx >> 6;                 // NTILES = 64
    int t = idx & (NTILES - 1);
    float tv = __uint_as_float(tmin_g[idx]);
    float gm = __uint_as_float(amin_g[m]);
    if (tv <= gm + MARGIN) {
        int p = atomicAdd(&cnt[t], 1);
        list[t * M_PTS + p] = m;
    }
}

// ---------------------------------------------------------------------------
// P2: exact fp32 rescore. Grid 128 = 64 tiles x 2 halves (64 codes each).
// Codes transposed in smem; per job: shfl-broadcast x dims, 2 codes per lane.
__global__ __launch_bounds__(256, 1)
void p2_kernel(const float* __restrict__ X, const float* __restrict__ E,
               const float* __restrict__ x2g, const float* __restrict__ e2g,
               const int* __restrict__ cnt_g, const int* __restrict__ list_g,
               ull* __restrict__ best) {
    extern __shared__ float sc[];     // sc[d * 66 + c], d<256, c<64; then e2[64]
    const int tile = blockIdx.x >> 1;
    const int half = blockIdx.x & 1;
    const int c0 = tile * BN + half * 64;
    const int tid = threadIdx.x;

    for (int i = tid; i < 64 * 256; i += 256) {
        int c = i >> 8, d = i & 255;
        sc[d * P2_STRIDE + c] = E[(size_t)(c0 + c) * D_DIM + d];
    }
    float* se2 = sc + 256 * P2_STRIDE;
    if (tid < 64) se2[tid] = e2g[c0 + tid];
    __syncthreads();

    const int lane = tid & 31;
    const int wid = tid >> 5;
    const int cnt = cnt_g[tile];

    for (int pi = wid; pi < cnt; pi += 8) {
        int m = list_g[tile * M_PTS + pi];
        float xr[8];
#pragma unroll
        for (int j = 0; j < 8; j++) xr[j] = X[(size_t)m * D_DIM + j * 32 + lane];

        float a0 = 0.0f, a1 = 0.0f, b0 = 0.0f, b1 = 0.0f;
#pragma unroll
        for (int j = 0; j < 8; j++) {
#pragma unroll
            for (int l = 0; l < 32; l++) {
                float xd = __shfl_sync(0xFFFFFFFFu, xr[j], l);
                float2 ev = *(const float2*)&sc[(j * 32 + l) * P2_STRIDE + 2 * lane];
                if (j & 1) { b0 = __fmaf_rn(xd, ev.x, b0); b1 = __fmaf_rn(xd, ev.y, b1); }
                else       { a0 = __fmaf_rn(xd, ev.x, a0); a1 = __fmaf_rn(xd, ev.y, a1); }
            }
        }
        float xe0 = __fadd_rn(a0, b0);
        float xe1 = __fadd_rn(a1, b1);

        float x2v = x2g[m];
        float d20 = __fadd_rn(__fadd_rn(x2v, -2.0f * xe0), se2[2 * lane]);
        float d21 = __fadd_rn(__fadd_rn(x2v, -2.0f * xe1), se2[2 * lane + 1]);
        ull k0 = ((ull)__float_as_uint(d20) << 32) | (u32)(c0 + 2 * lane);
        ull k1 = ((ull)__float_as_uint(d21) << 32) | (u32)(c0 + 2 * lane + 1);
        ull kb = (k1 < k0) ? k1 : k0;
#pragma unroll
        for (int o = 16; o >= 1; o >>= 1) {
            ull other = __shfl_xor_sync(0xFFFFFFFFu, kb, o);
            kb = (other < kb) ? other : kb;
        }
        if (lane == 0) atomicMin(&best[m], kb);
    }
}

// ---------------------------------------------------------------------------
__global__ void finalize_kernel(const float* __restrict__ E,
                                const ull* __restrict__ best,
                                float* __restrict__ out_q,
                                float* __restrict__ out_ind, int write_ind) {
    int row = blockIdx.x * (blockDim.x >> 5) + (threadIdx.x >> 5);
    int lane = threadIdx.x & 31;
    if (row >= M_PTS) return;
    u32 idx = (u32)(best[row] & 0xFFFFFFFFu);
    const float4* src = (const float4*)(E + (size_t)idx * D_DIM);
    float4* dst = (float4*)(out_q + (size_t)row * D_DIM);
    dst[lane]      = src[lane];
    dst[lane + 32] = src[lane + 32];
    if (write_ind && lane == 0) out_ind[row] = (float)idx;
}

// ---------------------------------------------------------------------------
extern "C" void kernel_launch(void* const* d_in, const int* in_sizes, int n_in,
                              void* d_out, int out_size) {
    const float* X = (const float*)d_in[0];
    const float* E = (const float*)d_in[1];
    if (n_in >= 2 && in_sizes[0] == C_CODES * D_DIM && in_sizes[1] == M_PTS * D_DIM) {
        X = (const float*)d_in[1];
        E = (const float*)d_in[0];
    }

    float* out_q = (float*)d_out;
    int write_ind = (out_size >= M_PTS * D_DIM + M_PTS) ? 1 : 0;
    float* out_ind = out_q + (size_t)M_PTS * D_DIM;

    ull* best; u32 *amin, *tmin; int *cnt, *list;
    float *x2p, *e2p; __half *xh, *eh;
    cudaGetSymbolAddress((void**)&best, g_best);
    cudaGetSymbolAddress((void**)&amin, g_amin);
    cudaGetSymbolAddress((void**)&tmin, g_tmin);
    cudaGetSymbolAddress((void**)&cnt, g_cnt);
    cudaGetSymbolAddress((void**)&list, g_list);
    cudaGetSymbolAddress((void**)&x2p, g_x2);
    cudaGetSymbolAddress((void**)&e2p, g_e2);
    cudaGetSymbolAddress((void**)&xh, g_Xh);
    cudaGetSymbolAddress((void**)&eh, g_Eh);

    init_kernel<<<(M_PTS + 255) / 256, 256>>>(best, amin, cnt);
    rowsumsq_kernel<<<(M_PTS + 7) / 8, 256>>>(X, x2p, M_PTS);
    rowsumsq_kernel<<<(C_CODES + 7) / 8, 256>>>(E, e2p, C_CODES);
    split_hi_kernel<<<(M_PTS * 64 + 255) / 256, 256>>>(X, xh, M_PTS * 64);
    split_hi_kernel<<<(C_CODES * 64 + 255) / 256, 256>>>(E, eh, C_CODES * 64);

    cudaFuncSetAttribute(p1_kernel, cudaFuncAttributeMaxDynamicSharedMemorySize, SMEM_P1);
    dim3 g1(NTILES, M_PTS / BM);
    p1_kernel<<<g1, 256, SMEM_P1>>>(x2p, e2p, tmin, amin);

    select_kernel<<<(M_PTS * NTILES + 255) / 256, 256>>>(tmin, amin, cnt, list);

    cudaFuncSetAttribute(p2_kernel, cudaFuncAttributeMaxDynamicSharedMemorySize, SMEM_P2);
    p2_kernel<<<2 * NTILES, 256, SMEM_P2>>>(X, E, x2p, e2p, cnt, list, best);

    finalize_kernel<<<(M_PTS + 7) / 8, 256>>>(E, best, out_q, out_ind, write_ind);
}

// round 9
// speedup vs baseline: 2.0449x; 1.1128x over previous
#include <cuda_runtime.h>
#include <cuda_fp16.h>
#include <stdint.h>

typedef unsigned long long ull;
typedef unsigned int u32;

#define M_PTS 16384
#define D_DIM 256
#define C_CODES 8192

#define BM 128
#define BN 128
#define BK 32
#define NKB (D_DIM / BK)          // 8 k-chunks
#define STRIDE 40                 // halfs per smem row (padded, conflict-free)
#define NTILES (C_CODES / BN)     // 64 C-tiles of 128 codes
#define MARGIN 2.5e-3f            // >= 2x worst-case |d2_approx - d2_exact|
#define NSLICE 8                  // P2 load-balance slices per (tile, half)

// P1 stage: Ah + Bh only
#define OFF_AH 0
#define OFF_BH (BM * STRIDE)                      // 5120 halfs
#define STAGE_HALFS ((BM + BN) * STRIDE)          // 10240
#define STAGE_BYTES (STAGE_HALFS * 2)             // 20480
#define SMEM_P1 (2 * STAGE_BYTES + BN * 4 + BM * 4)   // + e2 + tmin = 41984

// P2: 64 codes transposed [256][66] + e2[64]
#define P2_STRIDE 66
#define SMEM_P2 (256 * P2_STRIDE * 4 + 64 * 4)    // 67840

// ---------------------------------------------------------------------------
// Static scratch (no cudaMalloc allowed)
__device__ __align__(16) __half g_Xh[M_PTS * D_DIM];
__device__ __align__(16) __half g_Eh[C_CODES * D_DIM];
__device__ ull   g_best[M_PTS];
__device__ u32   g_amin[M_PTS];
__device__ u32   g_tmin[M_PTS * NTILES];
__device__ int   g_cnt[NTILES];
__device__ int   g_list[NTILES * M_PTS];
__device__ float g_x2[M_PTS];
__device__ float g_e2[C_CODES];

// ---------------------------------------------------------------------------
__device__ __forceinline__ u32 smem_u32(const void* p) {
    u32 a;
    asm("{ .reg .u64 t; cvta.to.shared.u64 t, %1; cvt.u32.u64 %0, t; }" : "=r"(a) : "l"(p));
    return a;
}
__device__ __forceinline__ void cp16(u32 dst, const void* src) {
    asm volatile("cp.async.cg.shared.global [%0], [%1], 16;" :: "r"(dst), "l"(src));
}
__device__ __forceinline__ void cp_commit() {
    asm volatile("cp.async.commit_group;" ::: "memory");
}
template <int N>
__device__ __forceinline__ void cp_wait() {
    asm volatile("cp.async.wait_group %0;" :: "n"(N) : "memory");
}
__device__ __forceinline__ void mma16816(float* c, u32 a0, u32 a1, u32 a2, u32 a3,
                                         u32 b0, u32 b1) {
    asm volatile(
        "mma.sync.aligned.m16n8k16.row.col.f32.f16.f16.f32 "
        "{%0,%1,%2,%3}, {%4,%5,%6,%7}, {%8,%9}, {%0,%1,%2,%3};"
        : "+f"(c[0]), "+f"(c[1]), "+f"(c[2]), "+f"(c[3])
        : "r"(a0), "r"(a1), "r"(a2), "r"(a3), "r"(b0), "r"(b1));
}
__device__ __forceinline__ void ldsm_x4(u32* r, u32 addr) {
    asm volatile("ldmatrix.sync.aligned.m8n8.x4.shared.b16 {%0,%1,%2,%3}, [%4];"
                 : "=r"(r[0]), "=r"(r[1]), "=r"(r[2]), "=r"(r[3]) : "r"(addr));
}

// ---------------------------------------------------------------------------
__global__ void init_kernel(ull* best, u32* amin, int* cnt) {
    int i = blockIdx.x * blockDim.x + threadIdx.x;
    if (i < M_PTS) { best[i] = 0xFFFFFFFFFFFFFFFFull; amin[i] = 0xFFFFFFFFu; }
    if (i < NTILES) cnt[i] = 0;
}

// row sum of squares (exact recipe that gave rel_err == 0 since round 1)
__global__ void rowsumsq_kernel(const float* __restrict__ a, float* __restrict__ out, int rows) {
    int row = blockIdx.x * (blockDim.x >> 5) + (threadIdx.x >> 5);
    int lane = threadIdx.x & 31;
    if (row >= rows) return;
    const float* p = a + (size_t)row * D_DIM;
    float acc = 0.0f;
#pragma unroll
    for (int i = 0; i < D_DIM / 32; i++) {
        float v = p[lane + 32 * i];
        acc = __fadd_rn(acc, __fmul_rn(v, v));
    }
#pragma unroll
    for (int o = 16; o >= 1; o >>= 1)
        acc = __fadd_rn(acc, __shfl_down_sync(0xFFFFFFFFu, acc, o));
    if (lane == 0) out[row] = acc;
}

// fp32 -> hi fp16, row-major
__global__ void split_hi_kernel(const float* __restrict__ src, __half* __restrict__ dh, int n4) {
    int idx = blockIdx.x * blockDim.x + threadIdx.x;
    if (idx >= n4) return;
    float4 v = ((const float4*)src)[idx];
    __half2 a = __halves2half2(__float2half_rn(v.x), __float2half_rn(v.y));
    __half2 b = __halves2half2(__float2half_rn(v.z), __float2half_rn(v.w));
    uint2 p;
    p.x = *(u32*)&a;
    p.y = *(u32*)&b;
    *(uint2*)(dh + (size_t)idx * 4) = p;
}

// ---------------------------------------------------------------------------
// P1: hi-only HMMA GEMM -> per-(point, tile) approx-min + global approx-min.
// Grid (NTILES=64, M/BM=128) = 8192 CTAs, 256 threads, 2 CTAs/SM, no spill.
__global__ __launch_bounds__(256, 2)
void p1_kernel(const float* __restrict__ x2g, const float* __restrict__ e2g,
               u32* __restrict__ tmin_g, u32* __restrict__ amin_g) {
    extern __shared__ __half smh[];
    const u32 sb = smem_u32(smh);
    const int tid = threadIdx.x;
    const int lane = tid & 31;
    const int wid = tid >> 5;
    const int warp_m = wid & 1;       // 64-row halves
    const int warp_n = wid >> 1;      // 0..3 -> 32-col slices

    const int mrow0 = blockIdx.y * BM;
    const int tile = blockIdx.x;
    const int crow0 = tile * BN;

    float* e2s  = (float*)((char*)smh + 2 * STAGE_BYTES);
    u32* tmin_s = (u32*)((char*)smh + 2 * STAGE_BYTES + BN * 4);
    if (tid < BN) e2s[tid] = e2g[crow0 + tid];
    if (tid < BM) tmin_s[tid] = 0xFFFFFFFFu;

    // ---- cp.async stage loader: 1024 16B tasks, 4 per thread ----
    auto issue = [&](int kb) {
        u32 sbase = sb + (u32)(kb & 1) * STAGE_BYTES;
        int kcol = kb * BK;
#pragma unroll
        for (int i = 0; i < 4; i++) {
            int t = tid + i * 256;
            if (t < 512) {
                int r = t >> 2, c = t & 3;
                const __half* g = g_Xh + (size_t)(mrow0 + r) * D_DIM + kcol + c * 8;
                cp16(sbase + (u32)(OFF_AH + r * STRIDE + c * 8) * 2, g);
            } else {
                int t2 = t - 512;
                int r = t2 >> 2, c = t2 & 3;
                const __half* g = g_Eh + (size_t)(crow0 + r) * D_DIM + kcol + c * 8;
                cp16(sbase + (u32)(OFF_BH + r * STRIDE + c * 8) * 2, g);
            }
        }
        cp_commit();
    };

    float acc[4][4][4];
#pragma unroll
    for (int mt = 0; mt < 4; mt++)
#pragma unroll
        for (int nt = 0; nt < 4; nt++)
#pragma unroll
            for (int r = 0; r < 4; r++) acc[mt][nt][r] = 0.0f;

    issue(0);

    const int a_r = (lane & 7) + ((lane >> 3) & 1) * 8;
    const int a_k = (lane >> 4) * 8;
    const int b_r = (lane & 7) + (lane >> 4) * 8;
    const int b_k = ((lane >> 3) & 1) * 8;

    u32 aoff[4], boff[2];
#pragma unroll
    for (int mt = 0; mt < 4; mt++)
        aoff[mt] = (u32)((OFF_AH + (warp_m * 64 + mt * 16 + a_r) * STRIDE + a_k) * 2);
#pragma unroll
    for (int p = 0; p < 2; p++)
        boff[p] = (u32)((OFF_BH + (warp_n * 32 + p * 16 + b_r) * STRIDE + b_k) * 2);

    // Single-barrier 2-stage pipeline.
    for (int kb = 0; kb < NKB; kb++) {
        cp_wait<0>();
        __syncthreads();
        if (kb + 1 < NKB) issue(kb + 1);

        const u32 sbase = sb + (u32)(kb & 1) * STAGE_BYTES;
#pragma unroll
        for (int ks = 0; ks < 2; ks++) {
            const u32 kbyte = (u32)(ks * 32);
            u32 af[4][4], bf[2][4];
#pragma unroll
            for (int mt = 0; mt < 4; mt++) ldsm_x4(af[mt], sbase + aoff[mt] + kbyte);
#pragma unroll
            for (int p = 0; p < 2; p++) ldsm_x4(bf[p], sbase + boff[p] + kbyte);
#pragma unroll
            for (int mt = 0; mt < 4; mt++)
#pragma unroll
                for (int nt = 0; nt < 4; nt++) {
                    const u32* b = bf[nt >> 1];
                    int o = (nt & 1) * 2;
                    mma16816(acc[mt][nt], af[mt][0], af[mt][1], af[mt][2], af[mt][3],
                             b[o], b[o + 1]);
                }
        }
    }
    __syncthreads();

    // ---- epilogue: approx d2, per-point tile-min via smem atomics ----
#pragma unroll
    for (int mt = 0; mt < 4; mt++) {
#pragma unroll
        for (int rh = 0; rh < 2; rh++) {
            int rlocal = warp_m * 64 + mt * 16 + rh * 8 + (lane >> 2);
            float x2v = x2g[mrow0 + rlocal];
            float vmin = 3.4e38f;
#pragma unroll
            for (int nt = 0; nt < 4; nt++) {
#pragma unroll
                for (int cc = 0; cc < 2; cc++) {
                    int cl = warp_n * 32 + nt * 8 + (lane & 3) * 2 + cc;
                    float t = __fadd_rn(x2v, -2.0f * acc[mt][nt][rh * 2 + cc]);
                    float d2 = __fadd_rn(t, e2s[cl]);
                    vmin = (d2 < vmin) ? d2 : vmin;
                }
            }
            atomicMin(&tmin_s[rlocal], __float_as_uint(vmin));
        }
    }
    __syncthreads();

    if (tid < BM) {
        u32 tb = tmin_s[tid];
        tmin_g[(size_t)(mrow0 + tid) * NTILES + tile] = tb;
        atomicMin(&amin_g[mrow0 + tid], tb);
    }
}

// ---------------------------------------------------------------------------
// Candidate tile selection.
__global__ void select_kernel(const u32* __restrict__ tmin_g, const u32* __restrict__ amin_g,
                              int* __restrict__ cnt, int* __restrict__ list) {
    int idx = blockIdx.x * blockDim.x + threadIdx.x;
    if (idx >= M_PTS * NTILES) return;
    int m = idx >> 6;                 // NTILES = 64
    int t = idx & (NTILES - 1);
    float tv = __uint_as_float(tmin_g[idx]);
    float gm = __uint_as_float(amin_g[m]);
    if (tv <= gm + MARGIN) {
        int p = atomicAdd(&cnt[t], 1);
        list[t * M_PTS + p] = m;
    }
}

// ---------------------------------------------------------------------------
// P2: exact fp32 rescore, load-balanced.
// Grid 1024 = 64 tiles x 2 halves x NSLICE slices. Each warp strides the
// tile's job list by 8 warps * NSLICE slices = 64.
__global__ __launch_bounds__(256, 1)
void p2_kernel(const float* __restrict__ X, const float* __restrict__ E,
               const float* __restrict__ x2g, const float* __restrict__ e2g,
               const int* __restrict__ cnt_g, const int* __restrict__ list_g,
               ull* __restrict__ best) {
    extern __shared__ float sc[];     // sc[d * 66 + c], d<256, c<64; then e2[64]
    const int tile  = blockIdx.x >> 4;          // /(2*NSLICE)
    const int half  = (blockIdx.x >> 3) & 1;
    const int slice = blockIdx.x & (NSLICE - 1);
    const int c0 = tile * BN + half * 64;
    const int tid = threadIdx.x;

    for (int i = tid; i < 64 * 256; i += 256) {
        int c = i >> 8, d = i & 255;
        sc[d * P2_STRIDE + c] = E[(size_t)(c0 + c) * D_DIM + d];
    }
    float* se2 = sc + 256 * P2_STRIDE;
    if (tid < 64) se2[tid] = e2g[c0 + tid];
    __syncthreads();

    const int lane = tid & 31;
    const int wid = tid >> 5;
    const int cnt = cnt_g[tile];

    for (int pi = slice * 8 + wid; pi < cnt; pi += 8 * NSLICE) {
        int m = list_g[tile * M_PTS + pi];
        float xr[8];
#pragma unroll
        for (int j = 0; j < 8; j++) xr[j] = X[(size_t)m * D_DIM + j * 32 + lane];

        float a0 = 0.0f, a1 = 0.0f, b0 = 0.0f, b1 = 0.0f;
#pragma unroll
        for (int j = 0; j < 8; j++) {
#pragma unroll
            for (int l = 0; l < 32; l++) {
                float xd = __shfl_sync(0xFFFFFFFFu, xr[j], l);
                float2 ev = *(const float2*)&sc[(j * 32 + l) * P2_STRIDE + 2 * lane];
                if (j & 1) { b0 = __fmaf_rn(xd, ev.x, b0); b1 = __fmaf_rn(xd, ev.y, b1); }
                else       { a0 = __fmaf_rn(xd, ev.x, a0); a1 = __fmaf_rn(xd, ev.y, a1); }
            }
        }
        float xe0 = __fadd_rn(a0, b0);
        float xe1 = __fadd_rn(a1, b1);

        float x2v = x2g[m];
        float d20 = __fadd_rn(__fadd_rn(x2v, -2.0f * xe0), se2[2 * lane]);
        float d21 = __fadd_rn(__fadd_rn(x2v, -2.0f * xe1), se2[2 * lane + 1]);
        ull k0 = ((ull)__float_as_uint(d20) << 32) | (u32)(c0 + 2 * lane);
        ull k1 = ((ull)__float_as_uint(d21) << 32) | (u32)(c0 + 2 * lane + 1);
        ull kb = (k1 < k0) ? k1 : k0;
#pragma unroll
        for (int o = 16; o >= 1; o >>= 1) {
            ull other = __shfl_xor_sync(0xFFFFFFFFu, kb, o);
            kb = (other < kb) ? other : kb;
        }
        if (lane == 0) atomicMin(&best[m], kb);
    }
}

// ---------------------------------------------------------------------------
__global__ void finalize_kernel(const float* __restrict__ E,
                                const ull* __restrict__ best,
                                float* __restrict__ out_q,
                                float* __restrict__ out_ind, int write_ind) {
    int row = blockIdx.x * (blockDim.x >> 5) + (threadIdx.x >> 5);
    int lane = threadIdx.x & 31;
    if (row >= M_PTS) return;
    u32 idx = (u32)(best[row] & 0xFFFFFFFFu);
    const float4* src = (const float4*)(E + (size_t)idx * D_DIM);
    float4* dst = (float4*)(out_q + (size_t)row * D_DIM);
    dst[lane]      = src[lane];
    dst[lane + 32] = src[lane + 32];
    if (write_ind && lane == 0) out_ind[row] = (float)idx;
}

// ---------------------------------------------------------------------------
extern "C" void kernel_launch(void* const* d_in, const int* in_sizes, int n_in,
                              void* d_out, int out_size) {
    const float* X = (const float*)d_in[0];
    const float* E = (const float*)d_in[1];
    if (n_in >= 2 && in_sizes[0] == C_CODES * D_DIM && in_sizes[1] == M_PTS * D_DIM) {
        X = (const float*)d_in[1];
        E = (const float*)d_in[0];
    }

    float* out_q = (float*)d_out;
    int write_ind = (out_size >= M_PTS * D_DIM + M_PTS) ? 1 : 0;
    float* out_ind = out_q + (size_t)M_PTS * D_DIM;

    ull* best; u32 *amin, *tmin; int *cnt, *list;
    float *x2p, *e2p; __half *xh, *eh;
    cudaGetSymbolAddress((void**)&best, g_best);
    cudaGetSymbolAddress((void**)&amin, g_amin);
    cudaGetSymbolAddress((void**)&tmin, g_tmin);
    cudaGetSymbolAddress((void**)&cnt, g_cnt);
    cudaGetSymbolAddress((void**)&list, g_list);
    cudaGetSymbolAddress((void**)&x2p, g_x2);
    cudaGetSymbolAddress((void**)&e2p, g_e2);
    cudaGetSymbolAddress((void**)&xh, g_Xh);
    cudaGetSymbolAddress((void**)&eh, g_Eh);

    init_kernel<<<(M_PTS + 255) / 256, 256>>>(best, amin, cnt);
    rowsumsq_kernel<<<(M_PTS + 7) / 8, 256>>>(X, x2p, M_PTS);
    rowsumsq_kernel<<<(C_CODES + 7) / 8, 256>>>(E, e2p, C_CODES);
    split_hi_kernel<<<(M_PTS * 64 + 255) / 256, 256>>>(X, xh, M_PTS * 64);
    split_hi_kernel<<<(C_CODES * 64 + 255) / 256, 256>>>(E, eh, C_CODES * 64);

    cudaFuncSetAttribute(p1_kernel, cudaFuncAttributeMaxDynamicSharedMemorySize, SMEM_P1);
    dim3 g1(NTILES, M_PTS / BM);
    p1_kernel<<<g1, 256, SMEM_P1>>>(x2p, e2p, tmin, amin);

    select_kernel<<<(M_PTS * NTILES + 255) / 256, 256>>>(tmin, amin, cnt, list);

    cudaFuncSetAttribute(p2_kernel, cudaFuncAttributeMaxDynamicSharedMemorySize, SMEM_P2);
    p2_kernel<<<2 * NSLICE * NTILES, 256, SMEM_P2>>>(X, E, x2p, e2p, cnt, list, best);

    finalize_kernel<<<(M_PTS + 7) / 8, 256>>>(E, best, out_q, out_ind, write_ind);
}

// round 10
// speedup vs baseline: 2.0758x; 1.0151x over previous
#include <cuda_runtime.h>
#include <cuda_fp16.h>
#include <stdint.h>

typedef unsigned long long ull;
typedef unsigned int u32;

#define M_PTS 16384
#define D_DIM 256
#define C_CODES 8192

#define BM 128
#define BN 128
#define BK 32
#define NKB (D_DIM / BK)          // 8 k-chunks
#define NSTAGE 3
#define STRIDE 40                 // halfs per smem row (padded, conflict-free)
#define NTILES (C_CODES / BN)     // 64 C-tiles of 128 codes
#define MARGIN 2.5e-3f            // >= 2x worst-case |d2_approx - d2_exact|
#define NSLICE 8                  // P2 load-balance slices per (tile, half)

// P1 stage: Ah + Bh only
#define OFF_AH 0
#define OFF_BH (BM * STRIDE)                      // 5120 halfs
#define STAGE_HALFS ((BM + BN) * STRIDE)          // 10240
#define STAGE_BYTES (STAGE_HALFS * 2)             // 20480
#define SMEM_P1 (NSTAGE * STAGE_BYTES + BN * 4 + BM * 4)   // 62464

// P2: 64 codes transposed [256][66] + e2[64]
#define P2_STRIDE 66
#define SMEM_P2 (256 * P2_STRIDE * 4 + 64 * 4)    // 67840

// ---------------------------------------------------------------------------
// Static scratch (no cudaMalloc allowed)
__device__ __align__(16) __half g_Xh[M_PTS * D_DIM];
__device__ __align__(16) __half g_Eh[C_CODES * D_DIM];
__device__ ull   g_best[M_PTS];
__device__ u32   g_amin[M_PTS];
__device__ u32   g_tmin[M_PTS * NTILES];
__device__ int   g_cnt[NTILES];
__device__ int   g_list[NTILES * M_PTS];
__device__ float g_x2[M_PTS];
__device__ float g_e2[C_CODES];

// ---------------------------------------------------------------------------
__device__ __forceinline__ u32 smem_u32(const void* p) {
    u32 a;
    asm("{ .reg .u64 t; cvta.to.shared.u64 t, %1; cvt.u32.u64 %0, t; }" : "=r"(a) : "l"(p));
    return a;
}
__device__ __forceinline__ void cp16(u32 dst, const void* src) {
    asm volatile("cp.async.cg.shared.global [%0], [%1], 16;" :: "r"(dst), "l"(src));
}
__device__ __forceinline__ void cp_commit() {
    asm volatile("cp.async.commit_group;" ::: "memory");
}
template <int N>
__device__ __forceinline__ void cp_wait() {
    asm volatile("cp.async.wait_group %0;" :: "n"(N) : "memory");
}
__device__ __forceinline__ void mma16816(float* c, u32 a0, u32 a1, u32 a2, u32 a3,
                                         u32 b0, u32 b1) {
    asm volatile(
        "mma.sync.aligned.m16n8k16.row.col.f32.f16.f16.f32 "
        "{%0,%1,%2,%3}, {%4,%5,%6,%7}, {%8,%9}, {%0,%1,%2,%3};"
        : "+f"(c[0]), "+f"(c[1]), "+f"(c[2]), "+f"(c[3])
        : "r"(a0), "r"(a1), "r"(a2), "r"(a3), "r"(b0), "r"(b1));
}
__device__ __forceinline__ void ldsm_x4(u32* r, u32 addr) {
    asm volatile("ldmatrix.sync.aligned.m8n8.x4.shared.b16 {%0,%1,%2,%3}, [%4];"
                 : "=r"(r[0]), "=r"(r[1]), "=r"(r[2]), "=r"(r[3]) : "r"(addr));
}

// ---------------------------------------------------------------------------
__global__ void init_kernel(ull* best, u32* amin, int* cnt) {
    int i = blockIdx.x * blockDim.x + threadIdx.x;
    if (i < M_PTS) { best[i] = 0xFFFFFFFFFFFFFFFFull; amin[i] = 0xFFFFFFFFu; }
    if (i < NTILES) cnt[i] = 0;
}

// row sum of squares (exact recipe that gave rel_err == 0 since round 1)
__global__ void rowsumsq_kernel(const float* __restrict__ a, float* __restrict__ out, int rows) {
    int row = blockIdx.x * (blockDim.x >> 5) + (threadIdx.x >> 5);
    int lane = threadIdx.x & 31;
    if (row >= rows) return;
    const float* p = a + (size_t)row * D_DIM;
    float acc = 0.0f;
#pragma unroll
    for (int i = 0; i < D_DIM / 32; i++) {
        float v = p[lane + 32 * i];
        acc = __fadd_rn(acc, __fmul_rn(v, v));
    }
#pragma unroll
    for (int o = 16; o >= 1; o >>= 1)
        acc = __fadd_rn(acc, __shfl_down_sync(0xFFFFFFFFu, acc, o));
    if (lane == 0) out[row] = acc;
}

// fp32 -> hi fp16, row-major
__global__ void split_hi_kernel(const float* __restrict__ src, __half* __restrict__ dh, int n4) {
    int idx = blockIdx.x * blockDim.x + threadIdx.x;
    if (idx >= n4) return;
    float4 v = ((const float4*)src)[idx];
    __half2 a = __halves2half2(__float2half_rn(v.x), __float2half_rn(v.y));
    __half2 b = __halves2half2(__float2half_rn(v.z), __float2half_rn(v.w));
    uint2 p;
    p.x = *(u32*)&a;
    p.y = *(u32*)&b;
    *(uint2*)(dh + (size_t)idx * 4) = p;
}

// ---------------------------------------------------------------------------
// P1: hi-only HMMA GEMM -> per-(point, tile) approx-min + global approx-min.
// Grid (NTILES=64, M/BM=128) = 8192 CTAs, 256 threads, 2 CTAs/SM, 3-stage pipe.
__global__ __launch_bounds__(256, 2)
void p1_kernel(const float* __restrict__ x2g, const float* __restrict__ e2g,
               u32* __restrict__ tmin_g, u32* __restrict__ amin_g) {
    extern __shared__ __half smh[];
    const u32 sb = smem_u32(smh);
    const int tid = threadIdx.x;
    const int lane = tid & 31;
    const int wid = tid >> 5;
    const int warp_m = wid & 1;       // 64-row halves
    const int warp_n = wid >> 1;      // 0..3 -> 32-col slices

    const int mrow0 = blockIdx.y * BM;
    const int tile = blockIdx.x;
    const int crow0 = tile * BN;

    float* e2s  = (float*)((char*)smh + NSTAGE * STAGE_BYTES);
    u32* tmin_s = (u32*)((char*)smh + NSTAGE * STAGE_BYTES + BN * 4);
    if (tid < BN) e2s[tid] = e2g[crow0 + tid];
    if (tid < BM) tmin_s[tid] = 0xFFFFFFFFu;

    // ---- cp.async stage loader: 1024 16B tasks, 4 per thread ----
    auto issue = [&](int kb) {
        u32 sbase = sb + (u32)(kb % NSTAGE) * STAGE_BYTES;
        int kcol = kb * BK;
#pragma unroll
        for (int i = 0; i < 4; i++) {
            int t = tid + i * 256;
            if (t < 512) {
                int r = t >> 2, c = t & 3;
                const __half* g = g_Xh + (size_t)(mrow0 + r) * D_DIM + kcol + c * 8;
                cp16(sbase + (u32)(OFF_AH + r * STRIDE + c * 8) * 2, g);
            } else {
                int t2 = t - 512;
                int r = t2 >> 2, c = t2 & 3;
                const __half* g = g_Eh + (size_t)(crow0 + r) * D_DIM + kcol + c * 8;
                cp16(sbase + (u32)(OFF_BH + r * STRIDE + c * 8) * 2, g);
            }
        }
        cp_commit();
    };

    float acc[4][4][4];
#pragma unroll
    for (int mt = 0; mt < 4; mt++)
#pragma unroll
        for (int nt = 0; nt < 4; nt++)
#pragma unroll
            for (int r = 0; r < 4; r++) acc[mt][nt][r] = 0.0f;

    issue(0);
    issue(1);

    const int a_r = (lane & 7) + ((lane >> 3) & 1) * 8;
    const int a_k = (lane >> 4) * 8;
    const int b_r = (lane & 7) + (lane >> 4) * 8;
    const int b_k = ((lane >> 3) & 1) * 8;

    u32 aoff[4], boff[2];
#pragma unroll
    for (int mt = 0; mt < 4; mt++)
        aoff[mt] = (u32)((OFF_AH + (warp_m * 64 + mt * 16 + a_r) * STRIDE + a_k) * 2);
#pragma unroll
    for (int p = 0; p < 2; p++)
        boff[p] = (u32)((OFF_BH + (warp_n * 32 + p * 16 + b_r) * STRIDE + b_k) * 2);

    // 3-stage pipeline: wait leaves the newest group in flight, so each copy
    // has ~2 compute blocks to land. Reads of stage (kb+2)%3 finished in iter
    // kb-1, before this iter's barrier, so issue(kb+2) can't clobber them.
    for (int kb = 0; kb < NKB; kb++) {
        if (kb + 1 < NKB) cp_wait<1>(); else cp_wait<0>();
        __syncthreads();
        if (kb + 2 < NKB) issue(kb + 2);

        const u32 sbase = sb + (u32)(kb % NSTAGE) * STAGE_BYTES;
#pragma unroll
        for (int ks = 0; ks < 2; ks++) {
            const u32 kbyte = (u32)(ks * 32);
            u32 af[4][4], bf[2][4];
#pragma unroll
            for (int mt = 0; mt < 4; mt++) ldsm_x4(af[mt], sbase + aoff[mt] + kbyte);
#pragma unroll
            for (int p = 0; p < 2; p++) ldsm_x4(bf[p], sbase + boff[p] + kbyte);
#pragma unroll
            for (int mt = 0; mt < 4; mt++)
#pragma unroll
                for (int nt = 0; nt < 4; nt++) {
                    const u32* b = bf[nt >> 1];
                    int o = (nt & 1) * 2;
                    mma16816(acc[mt][nt], af[mt][0], af[mt][1], af[mt][2], af[mt][3],
                             b[o], b[o + 1]);
                }
        }
    }
    __syncthreads();

    // ---- epilogue: approx d2, per-point tile-min via smem atomics ----
#pragma unroll
    for (int mt = 0; mt < 4; mt++) {
#pragma unroll
        for (int rh = 0; rh < 2; rh++) {
            int rlocal = warp_m * 64 + mt * 16 + rh * 8 + (lane >> 2);
            float x2v = x2g[mrow0 + rlocal];
            float vmin = 3.4e38f;
#pragma unroll
            for (int nt = 0; nt < 4; nt++) {
#pragma unroll
                for (int cc = 0; cc < 2; cc++) {
                    int cl = warp_n * 32 + nt * 8 + (lane & 3) * 2 + cc;
                    float t = __fadd_rn(x2v, -2.0f * acc[mt][nt][rh * 2 + cc]);
                    float d2 = __fadd_rn(t, e2s[cl]);
                    vmin = (d2 < vmin) ? d2 : vmin;
                }
            }
            atomicMin(&tmin_s[rlocal], __float_as_uint(vmin));
        }
    }
    __syncthreads();

    if (tid < BM) {
        u32 tb = tmin_s[tid];
        tmin_g[(size_t)(mrow0 + tid) * NTILES + tile] = tb;
        atomicMin(&amin_g[mrow0 + tid], tb);
    }
}

// ---------------------------------------------------------------------------
// Candidate tile selection.
__global__ void select_kernel(const u32* __restrict__ tmin_g, const u32* __restrict__ amin_g,
                              int* __restrict__ cnt, int* __restrict__ list) {
    int idx = blockIdx.x * blockDim.x + threadIdx.x;
    if (idx >= M_PTS * NTILES) return;
    int m = idx >> 6;                 // NTILES = 64
    int t = idx & (NTILES - 1);
    float tv = __uint_as_float(tmin_g[idx]);
    float gm = __uint_as_float(amin_g[m]);
    if (tv <= gm + MARGIN) {
        int p = atomicAdd(&cnt[t], 1);
        list[t * M_PTS + p] = m;
    }
}

// ---------------------------------------------------------------------------
// P2: exact fp32 rescore, load-balanced.
// Grid 1024 = 64 tiles x 2 halves x NSLICE slices.
__global__ __launch_bounds__(256, 1)
void p2_kernel(const float* __restrict__ X, const float* __restrict__ E,
               const float* __restrict__ x2g, const float* __restrict__ e2g,
               const int* __restrict__ cnt_g, const int* __restrict__ list_g,
               ull* __restrict__ best) {
    extern __shared__ float sc[];     // sc[d * 66 + c], d<256, c<64; then e2[64]
    const int tile  = blockIdx.x >> 4;          // /(2*NSLICE)
    const int half  = (blockIdx.x >> 3) & 1;
    const int slice = blockIdx.x & (NSLICE - 1);
    const int c0 = tile * BN + half * 64;
    const int tid = threadIdx.x;

    for (int i = tid; i < 64 * 256; i += 256) {
        int c = i >> 8, d = i & 255;
        sc[d * P2_STRIDE + c] = E[(size_t)(c0 + c) * D_DIM + d];
    }
    float* se2 = sc + 256 * P2_STRIDE;
    if (tid < 64) se2[tid] = e2g[c0 + tid];
    __syncthreads();

    const int lane = tid & 31;
    const int wid = tid >> 5;
    const int cnt = cnt_g[tile];

    for (int pi = slice * 8 + wid; pi < cnt; pi += 8 * NSLICE) {
        int m = list_g[tile * M_PTS + pi];
        float xr[8];
#pragma unroll
        for (int j = 0; j < 8; j++) xr[j] = X[(size_t)m * D_DIM + j * 32 + lane];

        float a0 = 0.0f, a1 = 0.0f, b0 = 0.0f, b1 = 0.0f;
#pragma unroll
        for (int j = 0; j < 8; j++) {
#pragma unroll
            for (int l = 0; l < 32; l++) {
                float xd = __shfl_sync(0xFFFFFFFFu, xr[j], l);
                float2 ev = *(const float2*)&sc[(j * 32 + l) * P2_STRIDE + 2 * lane];
                if (j & 1) { b0 = __fmaf_rn(xd, ev.x, b0); b1 = __fmaf_rn(xd, ev.y, b1); }
                else       { a0 = __fmaf_rn(xd, ev.x, a0); a1 = __fmaf_rn(xd, ev.y, a1); }
            }
        }
        float xe0 = __fadd_rn(a0, b0);
        float xe1 = __fadd_rn(a1, b1);

        float x2v = x2g[m];
        float d20 = __fadd_rn(__fadd_rn(x2v, -2.0f * xe0), se2[2 * lane]);
        float d21 = __fadd_rn(__fadd_rn(x2v, -2.0f * xe1), se2[2 * lane + 1]);
        ull k0 = ((ull)__float_as_uint(d20) << 32) | (u32)(c0 + 2 * lane);
        ull k1 = ((ull)__float_as_uint(d21) << 32) | (u32)(c0 + 2 * lane + 1);
        ull kb = (k1 < k0) ? k1 : k0;
#pragma unroll
        for (int o = 16; o >= 1; o >>= 1) {
            ull other = __shfl_xor_sync(0xFFFFFFFFu, kb, o);
            kb = (other < kb) ? other : kb;
        }
        if (lane == 0) atomicMin(&best[m], kb);
    }
}

// ---------------------------------------------------------------------------
__global__ void finalize_kernel(const float* __restrict__ E,
                                const ull* __restrict__ best,
                                float* __restrict__ out_q,
                                float* __restrict__ out_ind, int write_ind) {
    int row = blockIdx.x * (blockDim.x >> 5) + (threadIdx.x >> 5);
    int lane = threadIdx.x & 31;
    if (row >= M_PTS) return;
    u32 idx = (u32)(best[row] & 0xFFFFFFFFu);
    const float4* src = (const float4*)(E + (size_t)idx * D_DIM);
    float4* dst = (float4*)(out_q + (size_t)row * D_DIM);
    dst[lane]      = src[lane];
    dst[lane + 32] = src[lane + 32];
    if (write_ind && lane == 0) out_ind[row] = (float)idx;
}

// ---------------------------------------------------------------------------
extern "C" void kernel_launch(void* const* d_in, const int* in_sizes, int n_in,
                              void* d_out, int out_size) {
    const float* X = (const float*)d_in[0];
    const float* E = (const float*)d_in[1];
    if (n_in >= 2 && in_sizes[0] == C_CODES * D_DIM && in_sizes[1] == M_PTS * D_DIM) {
        X = (const float*)d_in[1];
        E = (const float*)d_in[0];
    }

    float* out_q = (float*)d_out;
    int write_ind = (out_size >= M_PTS * D_DIM + M_PTS) ? 1 : 0;
    float* out_ind = out_q + (size_t)M_PTS * D_DIM;

    ull* best; u32 *amin, *tmin; int *cnt, *list;
    float *x2p, *e2p; __half *xh, *eh;
    cudaGetSymbolAddress((void**)&best, g_best);
    cudaGetSymbolAddress((void**)&amin, g_amin);
    cudaGetSymbolAddress((void**)&tmin, g_tmin);
    cudaGetSymbolAddress((void**)&cnt, g_cnt);
    cudaGetSymbolAddress((void**)&list, g_list);
    cudaGetSymbolAddress((void**)&x2p, g_x2);
    cudaGetSymbolAddress((void**)&e2p, g_e2);
    cudaGetSymbolAddress((void**)&xh, g_Xh);
    cudaGetSymbolAddress((void**)&eh, g_Eh);

    init_kernel<<<(M_PTS + 255) / 256, 256>>>(best, amin, cnt);
    rowsumsq_kernel<<<(M_PTS + 7) / 8, 256>>>(X, x2p, M_PTS);
    rowsumsq_kernel<<<(C_CODES + 7) / 8, 256>>>(E, e2p, C_CODES);
    split_hi_kernel<<<(M_PTS * 64 + 255) / 256, 256>>>(X, xh, M_PTS * 64);
    split_hi_kernel<<<(C_CODES * 64 + 255) / 256, 256>>>(E, eh, C_CODES * 64);

    cudaFuncSetAttribute(p1_kernel, cudaFuncAttributeMaxDynamicSharedMemorySize, SMEM_P1);
    dim3 g1(NTILES, M_PTS / BM);
    p1_kernel<<<g1, 256, SMEM_P1>>>(x2p, e2p, tmin, amin);

    select_kernel<<<(M_PTS * NTILES + 255) / 256, 256>>>(tmin, amin, cnt, list);

    cudaFuncSetAttribute(p2_kernel, cudaFuncAttributeMaxDynamicSharedMemorySize, SMEM_P2);
    p2_kernel<<<2 * NSLICE * NTILES, 256, SMEM_P2>>>(X, E, x2p, e2p, cnt, list, best);

    finalize_kernel<<<(M_PTS + 7) / 8, 256>>>(E, best, out_q, out_ind, write_ind);
}